// round 15
// baseline (speedup 1.0000x reference)
#include <cuda_runtime.h>
#include <cuda_fp16.h>
#include <math.h>

// ---------------- problem constants ----------------
#define BB    16
#define LSEQ  2048
#define BL    (BB*LSEQ)        // 32768
#define DM    128
#define HH    4
#define HDIM  32
#define FFD   256
#define C1    128
#define C2    256
#define KK    5
#define L2HALF 1024
#define L2OUT  1020
#define M2    (BB*L2OUT)       // 16320
#define EPSV  1e-5f
#define SCALE 0.17677669529663687f
#define SCALE2 0.25501650f     // SCALE * log2(e)

// ---------------- scratch ----------------
__device__ float  g_x0 [BL*DM];
__device__ __half g_x0h[BL*DM];
__device__ __half g_qkvh[BL*3*DM];
__device__ __half g_atth[BL*DM];
__device__ float  g_x1 [BL*DM];
__device__ __half g_x1h[BL*DM];
__device__ __half g_ff1h[BL*FFD];
__device__ __half g_x2h[BL*DM];
__device__ __half g_y1h[BL*C1];
__device__ __half g_p1h[BB*L2HALF*C1];
__device__ __half g_y2h[M2*C2];
__device__ float  g_z  [BB*C2];
__device__ float  g_stats[2*C1 + 2*C2];
// fp16 weight pool: inw(49152) opw(16384) l1w(32768) l2w(32768) c1w(81920) c2w(163840) = 376832
// conv weights repacked k-major: w2[co][k*Cin+ci] = w[co][ci][k]
__device__ __half g_wh[376832];

// ---------------- helpers ----------------
__device__ __forceinline__ unsigned sptr(const void* p) {
    return (unsigned)__cvta_generic_to_shared(p);
}
__device__ __forceinline__ unsigned h2u(__half2 h) {
    unsigned u; asm("mov.b32 %0, %1;" : "=r"(u) : "r"(*(unsigned*)&h)); return u;
}
#define CP16(dst, src)      asm volatile("cp.async.cg.shared.global [%0], [%1], 16;" :: "r"(dst), "l"(src))
#define CP16Z(dst, src, sz) asm volatile("cp.async.cg.shared.global [%0], [%1], 16, %2;" :: "r"(dst), "l"(src), "r"(sz))
#define CP_COMMIT()    asm volatile("cp.async.commit_group;")
#define CP_WAIT1()     asm volatile("cp.async.wait_group 1;")
#define CP_WAIT0()     asm volatile("cp.async.wait_group 0;")

#define MMA_F16(C, a0,a1,a2,a3, b0,b1) \
    asm volatile("mma.sync.aligned.m16n8k16.row.col.f32.f16.f16.f32 " \
                 "{%0,%1,%2,%3},{%4,%5,%6,%7},{%8,%9},{%0,%1,%2,%3};" \
                 : "+f"((C)[0]),"+f"((C)[1]),"+f"((C)[2]),"+f"((C)[3]) \
                 : "r"(a0),"r"(a1),"r"(a2),"r"(a3),"r"(b0),"r"(b1))

#define LDSM4(R0,R1,R2,R3, A) \
    asm volatile("ldmatrix.sync.aligned.m8n8.x4.shared.b16 {%0,%1,%2,%3}, [%4];" \
                 : "=r"(R0),"=r"(R1),"=r"(R2),"=r"(R3) : "r"(A))
#define LDSM4T(R0,R1,R2,R3, A) \
    asm volatile("ldmatrix.sync.aligned.m8n8.x4.trans.shared.b16 {%0,%1,%2,%3}, [%4];" \
                 : "=r"(R0),"=r"(R1),"=r"(R2),"=r"(R3) : "r"(A))

// ---------------- merged f32 -> f16 weight conversion (+ conv k-major repack) ----------------
__global__ void f2h_all(const float* __restrict__ s0, const float* __restrict__ s1,
                        const float* __restrict__ s2, const float* __restrict__ s3,
                        const float* __restrict__ s4, const float* __restrict__ s5,
                        __half* __restrict__ dst)
{
    int i = blockIdx.x*256 + threadIdx.x;
    if (i < 49152)       dst[i] = __float2half_rn(s0[i]);
    else if (i < 65536)  dst[i] = __float2half_rn(s1[i - 49152]);
    else if (i < 98304)  dst[i] = __float2half_rn(s2[i - 65536]);
    else if (i < 131072) dst[i] = __float2half_rn(s3[i - 98304]);
    else if (i < 212992) {
        int j = i - 131072;                  // c1w: [128][640]
        int co = j / 640, rem = j % 640;
        int k = rem >> 7, ci = rem & 127;
        dst[i] = __float2half_rn(s4[co*640 + ci*5 + k]);
    } else if (i < 376832) {
        int j = i - 212992;                  // c2w: [256][640]
        int co = j / 640, rem = j % 640;
        int k = rem >> 7, c1 = rem & 127;
        dst[i] = __float2half_rn(s5[co*640 + c1*5 + k]);
    }
}

// ---------------- embed (writes f32 + f16) ----------------
__global__ void embed_kernel(const int* __restrict__ X, const float* __restrict__ sa,
                             const int* __restrict__ ptm,
                             const float* __restrict__ emb, const float* __restrict__ pemb,
                             float* __restrict__ x0, __half* __restrict__ x0h)
{
    int row = blockIdx.x;
    int t = threadIdx.x;
    float v;
    if (t < 120) v = emb[X[row]*120 + t] * sa[row];
    else         v = pemb[ptm[row]*8 + (t-120)];
    x0[(size_t)row*DM + t] = v;
    x0h[(size_t)row*DM + t] = __float2half_rn(v);
}

// ---------------- fp16 GEMM: 128x128 tile, 3-stage cp.async + ldmatrix ----------------
#define GSTH 40
__global__ __launch_bounds__(256,2) void gemm_f16(const __half* __restrict__ A,
                                                  const __half* __restrict__ W,
                                                  const float* __restrict__ bias,
                                                  float* __restrict__ Cf,
                                                  __half* __restrict__ Ch,
                                                  int M, int N, int K, int relu)
{
    __shared__ __align__(16) __half As[3][128*GSTH];
    __shared__ __align__(16) __half Bs[3][128*GSTH];
    int tid = threadIdx.x;
    int w = tid >> 5, lane = tid & 31, g = lane >> 2, tg = lane & 3;
    int wm = w & 3, wn = w >> 2;
    int row0 = blockIdx.y * 128, col0 = blockIdx.x * 128;

    int la = lane & 7, l8 = (lane >> 3) & 1, l16 = (lane >> 4) & 1;
    int rA = la + l8*8, cA = l16*8;
    int rB = la + l8*8, cB = l16*8;

    int lr = tid >> 2, lc8 = (tid & 3) * 8;
    int ar0 = row0 + lr;      if (ar0 > M-1) ar0 = M-1;
    int ar1 = row0 + lr + 64; if (ar1 > M-1) ar1 = M-1;
    const __half* ap0 = A + (size_t)ar0*K + lc8;
    const __half* ap1 = A + (size_t)ar1*K + lc8;
    const __half* wp0 = W + (size_t)(col0 + lr)*K + lc8;
    const __half* wp1 = W + (size_t)(col0 + lr + 64)*K + lc8;

    float c[2][8][4];
    #pragma unroll
    for (int mt=0; mt<2; ++mt)
        #pragma unroll
        for (int nt=0; nt<8; ++nt)
            #pragma unroll
            for (int i=0;i<4;++i) c[mt][nt][i]=0.f;

    int kt = K >> 5;

    #define GLOAD(s, k0) do { \
        CP16(sptr(&As[s][lr*GSTH + lc8]),      ap0 + (k0)); \
        CP16(sptr(&As[s][(lr+64)*GSTH + lc8]), ap1 + (k0)); \
        CP16(sptr(&Bs[s][lr*GSTH + lc8]),      wp0 + (k0)); \
        CP16(sptr(&Bs[s][(lr+64)*GSTH + lc8]), wp1 + (k0)); \
        CP_COMMIT(); \
    } while (0)

    GLOAD(0, 0);
    GLOAD(1, 32);

    for (int t = 0; t < kt; ++t) {
        int s = t % 3;
        CP_WAIT1();
        __syncthreads();
        if (t + 2 < kt) { GLOAD((t+2)%3, (t+2)*32); }
        else            { CP_COMMIT(); }

        #pragma unroll
        for (int ks = 0; ks < 2; ++ks) {
            int kk = ks*16;
            unsigned a[2][4], bq[4][4];
            #pragma unroll
            for (int mt = 0; mt < 2; ++mt)
                LDSM4(a[mt][0],a[mt][1],a[mt][2],a[mt][3],
                      sptr(&As[s][(wm*32 + mt*16 + rA)*GSTH + kk + cA]));
            #pragma unroll
            for (int p = 0; p < 4; ++p)
                LDSM4(bq[p][0],bq[p][1],bq[p][2],bq[p][3],
                      sptr(&Bs[s][(wn*64 + p*16 + rB)*GSTH + kk + cB]));
            #pragma unroll
            for (int p = 0; p < 4; ++p)
                #pragma unroll
                for (int q = 0; q < 2; ++q) {
                    int nt = p*2 + q;
                    MMA_F16(c[0][nt], a[0][0],a[0][1],a[0][2],a[0][3], bq[p][q], bq[p][q+2]);
                    MMA_F16(c[1][nt], a[1][0],a[1][1],a[1][2],a[1][3], bq[p][q], bq[p][q+2]);
                }
        }
    }
    #undef GLOAD

    #pragma unroll
    for (int mt = 0; mt < 2; ++mt) {
        int r0 = row0 + wm*32 + mt*16 + g;
        #pragma unroll
        for (int nt = 0; nt < 8; ++nt) {
            int cc = col0 + wn*64 + nt*8 + 2*tg;
            float b0v = bias[cc], b1v = bias[cc+1];
            float v0 = c[mt][nt][0] + b0v, v1 = c[mt][nt][1] + b1v;
            float v2 = c[mt][nt][2] + b0v, v3 = c[mt][nt][3] + b1v;
            if (relu) { v0=fmaxf(v0,0.f); v1=fmaxf(v1,0.f); v2=fmaxf(v2,0.f); v3=fmaxf(v3,0.f); }
            if (Cf) {
                if (r0 < M)     { float2 s2={v0,v1}; *(float2*)(Cf + (size_t)r0*N + cc) = s2; }
                if (r0 + 8 < M) { float2 s2={v2,v3}; *(float2*)(Cf + (size_t)(r0+8)*N + cc) = s2; }
            }
            if (Ch) {
                if (r0 < M)     *(__half2*)(Ch + (size_t)r0*N + cc)     = __floats2half2_rn(v0, v1);
                if (r0 + 8 < M) *(__half2*)(Ch + (size_t)(r0+8)*N + cc) = __floats2half2_rn(v2, v3);
            }
        }
    }
}

// ---------------- fp16 GEMM with fused residual + LayerNorm epilogue ----------------
// N == 128 (full row per block). out = LN(resid + A@W^T + bias). Writes outF (opt) + outH.
__global__ __launch_bounds__(256,2) void gemm_ln(const __half* __restrict__ A,
                                                 const __half* __restrict__ W,
                                                 const float* __restrict__ bias,
                                                 const float* __restrict__ resid,
                                                 const float* __restrict__ lng,
                                                 const float* __restrict__ lnb,
                                                 float* __restrict__ outF,
                                                 __half* __restrict__ outH,
                                                 int K)
{
    __shared__ __align__(16) __half As[3][128*GSTH];
    __shared__ __align__(16) __half Bs[3][128*GSTH];
    __shared__ float sSum[2][128], sSq[2][128];
    int tid = threadIdx.x;
    int w = tid >> 5, lane = tid & 31, g = lane >> 2, tg = lane & 3;
    int wm = w & 3, wn = w >> 2;
    int row0 = blockIdx.x * 128;

    int la = lane & 7, l8 = (lane >> 3) & 1, l16 = (lane >> 4) & 1;
    int rA = la + l8*8, cA = l16*8;
    int rB = la + l8*8, cB = l16*8;

    int lr = tid >> 2, lc8 = (tid & 3) * 8;
    const __half* ap0 = A + (size_t)(row0 + lr)*K + lc8;
    const __half* ap1 = A + (size_t)(row0 + lr + 64)*K + lc8;
    const __half* wp0 = W + (size_t)lr*K + lc8;
    const __half* wp1 = W + (size_t)(lr + 64)*K + lc8;

    float c[2][8][4];
    #pragma unroll
    for (int mt=0; mt<2; ++mt)
        #pragma unroll
        for (int nt=0; nt<8; ++nt)
            #pragma unroll
            for (int i=0;i<4;++i) c[mt][nt][i]=0.f;

    int kt = K >> 5;

    #define GLOAD(s, k0) do { \
        CP16(sptr(&As[s][lr*GSTH + lc8]),      ap0 + (k0)); \
        CP16(sptr(&As[s][(lr+64)*GSTH + lc8]), ap1 + (k0)); \
        CP16(sptr(&Bs[s][lr*GSTH + lc8]),      wp0 + (k0)); \
        CP16(sptr(&Bs[s][(lr+64)*GSTH + lc8]), wp1 + (k0)); \
        CP_COMMIT(); \
    } while (0)

    GLOAD(0, 0);
    GLOAD(1, 32);

    for (int t = 0; t < kt; ++t) {
        int s = t % 3;
        CP_WAIT1();
        __syncthreads();
        if (t + 2 < kt) { GLOAD((t+2)%3, (t+2)*32); }
        else            { CP_COMMIT(); }

        #pragma unroll
        for (int ks = 0; ks < 2; ++ks) {
            int kk = ks*16;
            unsigned a[2][4], bq[4][4];
            #pragma unroll
            for (int mt = 0; mt < 2; ++mt)
                LDSM4(a[mt][0],a[mt][1],a[mt][2],a[mt][3],
                      sptr(&As[s][(wm*32 + mt*16 + rA)*GSTH + kk + cA]));
            #pragma unroll
            for (int p = 0; p < 4; ++p)
                LDSM4(bq[p][0],bq[p][1],bq[p][2],bq[p][3],
                      sptr(&Bs[s][(wn*64 + p*16 + rB)*GSTH + kk + cB]));
            #pragma unroll
            for (int p = 0; p < 4; ++p)
                #pragma unroll
                for (int q = 0; q < 2; ++q) {
                    int nt = p*2 + q;
                    MMA_F16(c[0][nt], a[0][0],a[0][1],a[0][2],a[0][3], bq[p][q], bq[p][q+2]);
                    MMA_F16(c[1][nt], a[1][0],a[1][1],a[1][2],a[1][3], bq[p][q], bq[p][q+2]);
                }
        }
    }
    #undef GLOAD

    // add bias + residual into accumulators; compute per-row sums
    #pragma unroll
    for (int mt = 0; mt < 2; ++mt) {
        int lr0 = wm*32 + mt*16 + g;
        int r0 = row0 + lr0;
        float sA=0.f, qA=0.f, sB=0.f, qB=0.f;
        #pragma unroll
        for (int nt = 0; nt < 8; ++nt) {
            int cc = wn*64 + nt*8 + 2*tg;
            float2 b2 = *(const float2*)(bias + cc);
            float2 e0 = *(const float2*)(resid + (size_t)r0*DM + cc);
            float2 e1 = *(const float2*)(resid + (size_t)(r0+8)*DM + cc);
            c[mt][nt][0] += b2.x + e0.x;
            c[mt][nt][1] += b2.y + e0.y;
            c[mt][nt][2] += b2.x + e1.x;
            c[mt][nt][3] += b2.y + e1.y;
            sA += c[mt][nt][0] + c[mt][nt][1];
            qA += c[mt][nt][0]*c[mt][nt][0] + c[mt][nt][1]*c[mt][nt][1];
            sB += c[mt][nt][2] + c[mt][nt][3];
            qB += c[mt][nt][2]*c[mt][nt][2] + c[mt][nt][3]*c[mt][nt][3];
        }
        #pragma unroll
        for (int o2 = 1; o2 <= 2; o2 <<= 1) {
            sA += __shfl_xor_sync(0xffffffffu, sA, o2);
            qA += __shfl_xor_sync(0xffffffffu, qA, o2);
            sB += __shfl_xor_sync(0xffffffffu, sB, o2);
            qB += __shfl_xor_sync(0xffffffffu, qB, o2);
        }
        if (tg == 0) {
            sSum[wn][lr0] = sA;   sSq[wn][lr0] = qA;
            sSum[wn][lr0+8] = sB; sSq[wn][lr0+8] = qB;
        }
    }
    __syncthreads();

    #pragma unroll
    for (int mt = 0; mt < 2; ++mt) {
        int lr0 = wm*32 + mt*16 + g;
        int r0 = row0 + lr0;
        float s0 = sSum[0][lr0] + sSum[1][lr0];
        float q0 = sSq[0][lr0] + sSq[1][lr0];
        float s1 = sSum[0][lr0+8] + sSum[1][lr0+8];
        float q1 = sSq[0][lr0+8] + sSq[1][lr0+8];
        float mean0 = s0*(1.f/128.f), var0 = q0*(1.f/128.f) - mean0*mean0;
        float mean1 = s1*(1.f/128.f), var1 = q1*(1.f/128.f) - mean1*mean1;
        float f0 = rsqrtf(var0 + EPSV), f1 = rsqrtf(var1 + EPSV);
        #pragma unroll
        for (int nt = 0; nt < 8; ++nt) {
            int cc = wn*64 + nt*8 + 2*tg;
            float2 gg = *(const float2*)(lng + cc);
            float2 bb = *(const float2*)(lnb + cc);
            float o0 = (c[mt][nt][0]-mean0)*f0*gg.x + bb.x;
            float o1 = (c[mt][nt][1]-mean0)*f0*gg.y + bb.y;
            float o2 = (c[mt][nt][2]-mean1)*f1*gg.x + bb.x;
            float o3 = (c[mt][nt][3]-mean1)*f1*gg.y + bb.y;
            if (outF) {
                float2 t0={o0,o1}; *(float2*)(outF + (size_t)r0*DM + cc) = t0;
                float2 t1={o2,o3}; *(float2*)(outF + (size_t)(r0+8)*DM + cc) = t1;
            }
            *(__half2*)(outH + (size_t)r0*DM + cc)     = __floats2half2_rn(o0, o1);
            *(__half2*)(outH + (size_t)(r0+8)*DM + cc) = __floats2half2_rn(o2, o3);
        }
    }
}

// ---------------- direct conv GEMM (im2col-free), f16 output ----------------
__global__ __launch_bounds__(256,2) void conv_gemm_f16(const __half* __restrict__ src,
                                                       const __half* __restrict__ W,
                                                       const float* __restrict__ bias,
                                                       __half* __restrict__ Ch,
                                                       int M, int N, int Lin, int Lout, int pad)
{
    __shared__ __align__(16) __half As[3][128*GSTH];
    __shared__ __align__(16) __half Bs[3][128*GSTH];
    int tid = threadIdx.x;
    int w = tid >> 5, lane = tid & 31, g = lane >> 2, tg = lane & 3;
    int wm = w & 3, wn = w >> 2;
    int row0 = blockIdx.y * 128, col0 = blockIdx.x * 128;

    int la = lane & 7, l8 = (lane >> 3) & 1, l16 = (lane >> 4) & 1;
    int rA = la + l8*8, cA = l16*8;
    int rB = la + l8*8, cB = l16*8;

    int lr = tid >> 2, lc8 = (tid & 3) * 8;
    int r0g = row0 + lr;      if (r0g > M-1) r0g = M-1;
    int r1g = row0 + lr + 64; if (r1g > M-1) r1g = M-1;
    int b0 = r0g / Lout, l0 = r0g % Lout;
    int b1 = r1g / Lout, l1 = r1g % Lout;
    const __half* wp0 = W + (size_t)(col0 + lr)*640 + lc8;
    const __half* wp1 = W + (size_t)(col0 + lr + 64)*640 + lc8;

    float c[2][8][4];
    #pragma unroll
    for (int mt=0; mt<2; ++mt)
        #pragma unroll
        for (int nt=0; nt<8; ++nt)
            #pragma unroll
            for (int i=0;i<4;++i) c[mt][nt][i]=0.f;

    #define CGLOAD(s, t) do { \
        int k_ = (t) >> 2, coff_ = ((t) & 3) * 32; \
        int ls0 = l0 + k_ - pad; \
        int ls1 = l1 + k_ - pad; \
        unsigned ok0 = ((unsigned)ls0 < (unsigned)Lin) ? 16u : 0u; \
        unsigned ok1 = ((unsigned)ls1 < (unsigned)Lin) ? 16u : 0u; \
        const __half* s0_ = src + ((size_t)(b0*Lin + (ok0 ? ls0 : 0)))*128 + coff_ + lc8; \
        const __half* s1_ = src + ((size_t)(b1*Lin + (ok1 ? ls1 : 0)))*128 + coff_ + lc8; \
        CP16Z(sptr(&As[s][lr*GSTH + lc8]),      s0_, ok0); \
        CP16Z(sptr(&As[s][(lr+64)*GSTH + lc8]), s1_, ok1); \
        CP16(sptr(&Bs[s][lr*GSTH + lc8]),      wp0 + (t)*32); \
        CP16(sptr(&Bs[s][(lr+64)*GSTH + lc8]), wp1 + (t)*32); \
        CP_COMMIT(); \
    } while (0)

    CGLOAD(0, 0);
    CGLOAD(1, 1);

    for (int t = 0; t < 20; ++t) {
        int s = t % 3;
        CP_WAIT1();
        __syncthreads();
        if (t + 2 < 20) { CGLOAD((t+2)%3, t+2); }
        else            { CP_COMMIT(); }

        #pragma unroll
        for (int ks = 0; ks < 2; ++ks) {
            int kk = ks*16;
            unsigned a[2][4], bq[4][4];
            #pragma unroll
            for (int mt = 0; mt < 2; ++mt)
                LDSM4(a[mt][0],a[mt][1],a[mt][2],a[mt][3],
                      sptr(&As[s][(wm*32 + mt*16 + rA)*GSTH + kk + cA]));
            #pragma unroll
            for (int p = 0; p < 4; ++p)
                LDSM4(bq[p][0],bq[p][1],bq[p][2],bq[p][3],
                      sptr(&Bs[s][(wn*64 + p*16 + rB)*GSTH + kk + cB]));
            #pragma unroll
            for (int p = 0; p < 4; ++p)
                #pragma unroll
                for (int q = 0; q < 2; ++q) {
                    int nt = p*2 + q;
                    MMA_F16(c[0][nt], a[0][0],a[0][1],a[0][2],a[0][3], bq[p][q], bq[p][q+2]);
                    MMA_F16(c[1][nt], a[1][0],a[1][1],a[1][2],a[1][3], bq[p][q], bq[p][q+2]);
                }
        }
    }
    #undef CGLOAD

    #pragma unroll
    for (int mt = 0; mt < 2; ++mt) {
        int r0 = row0 + wm*32 + mt*16 + g;
        #pragma unroll
        for (int nt = 0; nt < 8; ++nt) {
            int cc = col0 + wn*64 + nt*8 + 2*tg;
            float b0v = bias[cc], b1v = bias[cc+1];
            float v0 = c[mt][nt][0] + b0v, v1 = c[mt][nt][1] + b1v;
            float v2 = c[mt][nt][2] + b0v, v3 = c[mt][nt][3] + b1v;
            if (r0 < M)     *(__half2*)(Ch + (size_t)r0*N + cc)     = __floats2half2_rn(v0, v1);
            if (r0 + 8 < M) *(__half2*)(Ch + (size_t)(r0+8)*N + cc) = __floats2half2_rn(v2, v3);
        }
    }
}

// ---------------- fp16 flash attention (round-11 proven) ----------------
#define KSTH 40
#define RSN  2176
__global__ __launch_bounds__(256,2) void attn_f16(const __half* __restrict__ qkv,
                                                  const float* __restrict__ rpe,
                                                  __half* __restrict__ o)
{
    __shared__ __align__(16) __half Ks[2][64*KSTH];
    __shared__ __align__(16) __half Vs[2][64*KSTH];
    __shared__ __half2 rsh2[RSN];

    int tid = threadIdx.x;
    int w = tid >> 5, lane = tid & 31, g = lane >> 2, tg = lane & 3;
    int b = blockIdx.z, h = blockIdx.y;
    int q0 = blockIdx.x * 128;

    for (int i = tid; i < RSN; i += 256) {
        int d0 = i - 127 - q0;     d0 = d0 < -32 ? -32 : (d0 > 32 ? 32 : d0);
        int d1 = i + 1 - 127 - q0; d1 = d1 < -32 ? -32 : (d1 > 32 ? 32 : d1);
        rsh2[i] = __floats2half2_rn(rpe[(d0 + 32)*HH + h] * 1.44269504f,
                                    rpe[(d1 + 32)*HH + h] * 1.44269504f);
    }

    int la = lane & 7, l8 = (lane >> 3) & 1, l16 = (lane >> 4) & 1;
    int rB = la + l8*8, cB = l16*8;

    int r0 = q0 + w*16 + g, r1 = r0 + 8;
    int rbase = 127 - (w*16 + g) + 2*tg;

    const unsigned sc2  = h2u(__floats2half2_rn(SCALE2, SCALE2));
    const unsigned cl15 = h2u(__floats2half2_rn(15.f, 15.f));
    const unsigned ones = h2u(__floats2half2_rn(1.f, 1.f));

    unsigned aq[2][4];
    {
        const __half* qb = qkv + (size_t)(b*LSEQ)*384 + h*HDIM;
        #pragma unroll
        for (int kc = 0; kc < 2; ++kc) {
            int k = kc*16;
            aq[kc][0] = *(const unsigned*)(qb + (size_t)r0*384 + k + 2*tg);
            aq[kc][1] = *(const unsigned*)(qb + (size_t)r1*384 + k + 2*tg);
            aq[kc][2] = *(const unsigned*)(qb + (size_t)r0*384 + k + 2*tg + 8);
            aq[kc][3] = *(const unsigned*)(qb + (size_t)r1*384 + k + 2*tg + 8);
        }
    }

    float co[4][4];
    #pragma unroll
    for (int nt=0;nt<4;++nt)
        #pragma unroll
        for (int i=0;i<4;++i) co[nt][i]=0.f;
    float csum[4] = {0.f, 0.f, 0.f, 0.f};

    int srow = tid >> 2, scol = (tid & 3) * 8;
    const __half* kvbase = qkv + (size_t)(b*LSEQ)*384 + h*HDIM + 128;

    #define STAGE(s, j0) do { \
        const __half* kb_ = kvbase + (size_t)((j0) + srow)*384; \
        CP16(sptr(&Ks[s][srow*KSTH + scol]), kb_ + scol); \
        CP16(sptr(&Vs[s][srow*KSTH + scol]), kb_ + 128 + scol); \
        CP_COMMIT(); \
    } while (0)

    STAGE(0, 0);

    for (int jt = 0; jt < LSEQ/64; ++jt) {
        int s = jt & 1;
        if (jt + 1 < LSEQ/64) { STAGE(s^1, (jt+1)*64); CP_WAIT1(); }
        else                  { CP_WAIT0(); }
        __syncthreads();

        float cs[8][4];
        #pragma unroll
        for (int nt=0;nt<8;++nt)
            #pragma unroll
            for (int i=0;i<4;++i) cs[nt][i]=0.f;
        #pragma unroll
        for (int kc = 0; kc < 2; ++kc) {
            int kk = kc*16;
            unsigned bq[4][4];
            #pragma unroll
            for (int p = 0; p < 4; ++p)
                LDSM4(bq[p][0],bq[p][1],bq[p][2],bq[p][3],
                      sptr(&Ks[s][(p*16 + rB)*KSTH + kk + cB]));
            #pragma unroll
            for (int p = 0; p < 4; ++p)
                #pragma unroll
                for (int q = 0; q < 2; ++q)
                    MMA_F16(cs[p*2+q], aq[kc][0],aq[kc][1],aq[kc][2],aq[kc][3],
                            bq[p][q], bq[p][q+2]);
        }

        int ixb = jt*64 + rbase;
        unsigned ap[4][4];
        #pragma unroll
        for (int nt = 0; nt < 8; ++nt) {
            int ix = ixb + nt*8;
            unsigned x01 = h2u(__floats2half2_rn(cs[nt][0], cs[nt][1]));
            unsigned x23 = h2u(__floats2half2_rn(cs[nt][2], cs[nt][3]));
            unsigned b01 = *(const unsigned*)&rsh2[ix];
            unsigned b23 = *(const unsigned*)&rsh2[ix-8];
            asm("fma.rn.f16x2 %0, %1, %2, %3;" : "=r"(x01) : "r"(x01), "r"(sc2), "r"(b01));
            asm("fma.rn.f16x2 %0, %1, %2, %3;" : "=r"(x23) : "r"(x23), "r"(sc2), "r"(b23));
            asm("min.f16x2 %0, %1, %2;" : "=r"(x01) : "r"(x01), "r"(cl15));
            asm("min.f16x2 %0, %1, %2;" : "=r"(x23) : "r"(x23), "r"(cl15));
            asm("ex2.approx.f16x2 %0, %1;" : "=r"(x01) : "r"(x01));
            asm("ex2.approx.f16x2 %0, %1;" : "=r"(x23) : "r"(x23));
            int ks = nt >> 1, hi = nt & 1;
            ap[ks][hi*2+0] = x01;
            ap[ks][hi*2+1] = x23;
        }

        #pragma unroll
        for (int ks = 0; ks < 4; ++ks)
            MMA_F16(csum, ap[ks][0],ap[ks][1],ap[ks][2],ap[ks][3], ones, ones);

        #pragma unroll
        for (int ks = 0; ks < 4; ++ks) {
            int kk = ks*16;
            unsigned bv[2][4];
            #pragma unroll
            for (int dg = 0; dg < 2; ++dg)
                LDSM4T(bv[dg][0],bv[dg][1],bv[dg][2],bv[dg][3],
                       sptr(&Vs[s][(kk + la + l8*8)*KSTH + dg*16 + l16*8]));
            #pragma unroll
            for (int dg = 0; dg < 2; ++dg)
                #pragma unroll
                for (int q = 0; q < 2; ++q)
                    MMA_F16(co[dg*2+q], ap[ks][0],ap[ks][1],ap[ks][2],ap[ks][3],
                            bv[dg][q*2], bv[dg][q*2+1]);
        }
        __syncthreads();
    }
    #undef STAGE

    float inv0 = 1.f / csum[0], inv1 = 1.f / csum[2];

    #pragma unroll
    for (int nt2 = 0; nt2 < 4; ++nt2) {
        int d = nt2*8 + 2*tg;
        *(__half2*)(o + ((size_t)(b*LSEQ + r0))*DM + h*HDIM + d) =
            __floats2half2_rn(co[nt2][0]*inv0, co[nt2][1]*inv0);
        *(__half2*)(o + ((size_t)(b*LSEQ + r1))*DM + h*HDIM + d) =
            __floats2half2_rn(co[nt2][2]*inv1, co[nt2][3]*inv1);
    }
}

// ---------------- BN stats (f16 input) ----------------
__global__ void bnstats_kernel(const __half* __restrict__ y, int rows, int Cc, int rpb,
                               float* __restrict__ sum, float* __restrict__ sumsq)
{
    int c = threadIdx.x;
    int r0 = blockIdx.x * rpb;
    int r1 = r0 + rpb; if (r1 > rows) r1 = rows;
    float s = 0.f, s2 = 0.f;
    for (int r = r0; r < r1; ++r) {
        float v = __half2float(y[(size_t)r*Cc + c]);
        s += v; s2 += v*v;
    }
    atomicAdd(&sum[c], s);
    atomicAdd(&sumsq[c], s2);
}

// zero stats (n1) and z (n2) in one launch
__global__ void zero2_kernel(float* p1, int n1, float* p2, int n2)
{
    int i = blockIdx.x*256 + threadIdx.x;
    if (i < n1) p1[i] = 0.f;
    if (i < n2) p2[i] = 0.f;
}

// ---------------- BN + ReLU + maxpool(2): f16 in -> f16 out ----------------
__global__ void bnpool_kernel(const __half* __restrict__ y1,
                              const float* __restrict__ sum, const float* __restrict__ sq,
                              const float* __restrict__ g, const float* __restrict__ bb,
                              __half* __restrict__ p1)
{
    int c = threadIdx.x;
    int row2 = blockIdx.x;
    int b = row2 >> 10, l2 = row2 & 1023;
    float mean = sum[c]*(1.f/(float)BL);
    float var  = sq[c]*(1.f/(float)BL) - mean*mean;
    float f = rsqrtf(var + EPSV)*g[c];
    float v0 = (__half2float(y1[((size_t)(b*LSEQ + 2*l2  ))*C1 + c]) - mean)*f + bb[c];
    float v1 = (__half2float(y1[((size_t)(b*LSEQ + 2*l2+1))*C1 + c]) - mean)*f + bb[c];
    v0 = fmaxf(v0, 0.f); v1 = fmaxf(v1, 0.f);
    p1[(size_t)row2*C1 + c] = __float2half_rn(fmaxf(v0, v1));
}

// ---------------- BN + ReLU + global max (f16 in, atomicMax) ----------------
__global__ void gmax_kernel(const __half* __restrict__ y2,
                            const float* __restrict__ sum, const float* __restrict__ sq,
                            const float* __restrict__ g, const float* __restrict__ bb,
                            float* __restrict__ z)
{
    int c = threadIdx.x;
    int b = blockIdx.x;
    int part = blockIdx.y;
    float mean = sum[c]*(1.f/(float)M2);
    float var  = sq[c]*(1.f/(float)M2) - mean*mean;
    float f = rsqrtf(var + EPSV)*g[c];
    int l0 = part * 128;
    int l1 = l0 + 128; if (l1 > L2OUT) l1 = L2OUT;
    float vm = 0.f;
    for (int l = l0; l < l1; ++l) {
        float v = (__half2float(y2[((size_t)(b*L2OUT + l))*C2 + c]) - mean)*f + bb[c];
        vm = fmaxf(vm, v);
    }
    vm = fmaxf(vm, 0.f);
    atomicMax((int*)&z[b*C2 + c], __float_as_int(vm));
}

// ---------------- final fc ----------------
__global__ void fc_kernel(const float* __restrict__ z, const float* __restrict__ w,
                          const float* __restrict__ bias, float* __restrict__ out)
{
    int b = blockIdx.x, n = blockIdx.y;
    int t = threadIdx.x;
    float p = z[b*C2 + t] * w[n*C2 + t];
    #pragma unroll
    for (int off = 16; off; off >>= 1) p += __shfl_xor_sync(0xffffffffu, p, off);
    __shared__ float ws[8];
    if ((t & 31) == 0) ws[t >> 5] = p;
    __syncthreads();
    if (t == 0) {
        float s = 0.f;
        #pragma unroll
        for (int i = 0; i < 8; ++i) s += ws[i];
        out[b*2 + n] = s + bias[n];
    }
}

// ---------------- launch ----------------
extern "C" void kernel_launch(void* const* d_in, const int* in_sizes, int n_in,
                              void* d_out, int out_size)
{
    const int*   X    = (const int*)  d_in[0];
    const float* sa   = (const float*)d_in[1];
    const int*   ptm  = (const int*)  d_in[2];
    const float* emb  = (const float*)d_in[3];
    const float* pemb = (const float*)d_in[4];
    const float* rpe  = (const float*)d_in[5];
    const float* inw  = (const float*)d_in[6];
    const float* inb  = (const float*)d_in[7];
    const float* opw  = (const float*)d_in[8];
    const float* opb  = (const float*)d_in[9];
    const float* l1w  = (const float*)d_in[10];
    const float* l1b  = (const float*)d_in[11];
    const float* l2w  = (const float*)d_in[12];
    const float* l2b  = (const float*)d_in[13];
    const float* ln1g = (const float*)d_in[14];
    const float* ln1b = (const float*)d_in[15];
    const float* ln2g = (const float*)d_in[16];
    const float* ln2b = (const float*)d_in[17];
    const float* c1w  = (const float*)d_in[18];
    const float* c1b  = (const float*)d_in[19];
    const float* bn1g = (const float*)d_in[20];
    const float* bn1b = (const float*)d_in[21];
    const float* c2w  = (const float*)d_in[22];
    const float* c2b  = (const float*)d_in[23];
    const float* bn2g = (const float*)d_in[24];
    const float* bn2b = (const float*)d_in[25];
    const float* fcw  = (const float*)d_in[26];
    const float* fcb  = (const float*)d_in[27];
    float* out = (float*)d_out;

    float *x0,*x1,*z,*stats;
    __half *x0h,*qkvh,*atth,*x1h,*ff1h,*x2h,*y1h,*p1h,*y2h,*wh;
    cudaGetSymbolAddress((void**)&x0,   g_x0);
    cudaGetSymbolAddress((void**)&x0h,  g_x0h);
    cudaGetSymbolAddress((void**)&qkvh, g_qkvh);
    cudaGetSymbolAddress((void**)&atth, g_atth);
    cudaGetSymbolAddress((void**)&x1,   g_x1);
    cudaGetSymbolAddress((void**)&x1h,  g_x1h);
    cudaGetSymbolAddress((void**)&ff1h, g_ff1h);
    cudaGetSymbolAddress((void**)&x2h,  g_x2h);
    cudaGetSymbolAddress((void**)&y1h,  g_y1h);
    cudaGetSymbolAddress((void**)&p1h,  g_p1h);
    cudaGetSymbolAddress((void**)&y2h,  g_y2h);
    cudaGetSymbolAddress((void**)&z,    g_z);
    cudaGetSymbolAddress((void**)&stats,g_stats);
    cudaGetSymbolAddress((void**)&wh,   g_wh);

    __half* inwh = wh;
    __half* opwh = wh + 49152;
    __half* l1wh = wh + 65536;
    __half* l2wh = wh + 98304;
    __half* c1wh = wh + 131072;
    __half* c2wh = wh + 212992;

    // 0) merged weight conversion (f32 -> f16, conv weights repacked k-major)
    f2h_all<<<(376832 + 255)/256, 256>>>(inw, opw, l1w, l2w, c1w, c2w, wh);

    // 1) embedding + concat (f32 + f16)
    embed_kernel<<<BL, 128>>>(X, sa, ptm, emb, pemb, x0, x0h);

    // 2) qkv projection -> f16 [BL,384]
    gemm_f16<<<dim3(384/128, BL/128), 256>>>(x0h, inwh, inb, nullptr, qkvh, BL, 3*DM, DM, 0);

    // 3) attention -> f16
    attn_f16<<<dim3(LSEQ/128, HH, BB), 256>>>(qkvh, rpe, atth);

    // 4) out-proj + residual + LN1 fused -> x1 (f32) + x1h
    gemm_ln<<<BL/128, 256>>>(atth, opwh, opb, x0, ln1g, ln1b, x1, x1h, DM);

    // 5) FF1
    gemm_f16<<<dim3(FFD/128, BL/128), 256>>>(x1h, l1wh, l1b, nullptr, ff1h, BL, FFD, DM, 1);

    // 6) FF2 + residual + LN2 fused -> x2h (f16 only)
    gemm_ln<<<BL/128, 256>>>(ff1h, l2wh, l2b, x1, ln2g, ln2b, nullptr, x2h, FFD);

    // 7) conv1 direct GEMM -> y1h (f16)
    conv_gemm_f16<<<dim3(C1/128, BL/128), 256>>>(x2h, c1wh, c1b, y1h, BL, C1, LSEQ, LSEQ, 2);

    // 8) zero stats + z, BN1 stats
    zero2_kernel<<<16, 256>>>(stats, 2*C1 + 2*C2, z, BB*C2);
    bnstats_kernel<<<128, C1>>>(y1h, BL, C1, 256, stats, stats + C1);

    // 9) BN1 + ReLU + maxpool2 -> f16 p1
    bnpool_kernel<<<BB*L2HALF, C1>>>(y1h, stats, stats + C1, bn1g, bn1b, p1h);

    // 10) conv2 direct GEMM -> y2h (f16)
    conv_gemm_f16<<<dim3(C2/128, (M2+127)/128), 256>>>(p1h, c2wh, c2b, y2h, M2, C2, L2HALF, L2OUT, 0);

    // 11) BN2 stats
    bnstats_kernel<<<128, C2>>>(y2h, M2, C2, 128, stats + 2*C1, stats + 2*C1 + C2);

    // 12) BN2 + ReLU + global max
    gmax_kernel<<<dim3(BB, 8), C2>>>(y2h, stats + 2*C1, stats + 2*C1 + C2, bn2g, bn2b, z);

    // 13) fc
    fc_kernel<<<dim3(BB, 2), 256>>>(z, fcw, fcb, out);
}

// round 16
// speedup vs baseline: 1.2438x; 1.2438x over previous
#include <cuda_runtime.h>
#include <cuda_fp16.h>
#include <math.h>

// ---------------- problem constants ----------------
#define BB    16
#define LSEQ  2048
#define BL    (BB*LSEQ)        // 32768
#define DM    128
#define HH    4
#define HDIM  32
#define FFD   256
#define C1    128
#define C2    256
#define KK    5
#define L2HALF 1024
#define L2OUT  1020
#define M2    (BB*L2OUT)       // 16320
#define EPSV  1e-5f
#define SCALE 0.17677669529663687f
#define SCALE2 0.25501650f     // SCALE * log2(e)

// ---------------- scratch ----------------
__device__ float  g_x0 [BL*DM];
__device__ __half g_x0h[BL*DM];
__device__ __half g_qkvh[BL*3*DM];
__device__ __half g_atth[BL*DM];
__device__ float  g_tmp[BL*DM];
__device__ float  g_x1 [BL*DM];
__device__ __half g_x1h[BL*DM];
__device__ __half g_ff1h[BL*FFD];
__device__ __half g_x2h[BL*DM];
__device__ __half g_y1h[BL*C1];
__device__ __half g_p1h[BB*L2HALF*C1];
__device__ __half g_y2h[M2*C2];
__device__ float  g_z  [BB*C2];
__device__ float  g_stats[2*C1 + 2*C2];
// fp16 weight pool: inw(49152) opw(16384) l1w(32768) l2w(32768) c1w(81920) c2w(163840) = 376832
// conv weights repacked k-major: w2[co][k*Cin+ci] = w[co][ci][k]
__device__ __half g_wh[376832];

// ---------------- helpers ----------------
__device__ __forceinline__ unsigned sptr(const void* p) {
    return (unsigned)__cvta_generic_to_shared(p);
}
__device__ __forceinline__ unsigned h2u(__half2 h) {
    unsigned u; asm("mov.b32 %0, %1;" : "=r"(u) : "r"(*(unsigned*)&h)); return u;
}
#define CP16(dst, src)      asm volatile("cp.async.cg.shared.global [%0], [%1], 16;" :: "r"(dst), "l"(src))
#define CP16Z(dst, src, sz) asm volatile("cp.async.cg.shared.global [%0], [%1], 16, %2;" :: "r"(dst), "l"(src), "r"(sz))
#define CP_COMMIT()    asm volatile("cp.async.commit_group;")
#define CP_WAIT1()     asm volatile("cp.async.wait_group 1;")
#define CP_WAIT0()     asm volatile("cp.async.wait_group 0;")

#define MMA_F16(C, a0,a1,a2,a3, b0,b1) \
    asm volatile("mma.sync.aligned.m16n8k16.row.col.f32.f16.f16.f32 " \
                 "{%0,%1,%2,%3},{%4,%5,%6,%7},{%8,%9},{%0,%1,%2,%3};" \
                 : "+f"((C)[0]),"+f"((C)[1]),"+f"((C)[2]),"+f"((C)[3]) \
                 : "r"(a0),"r"(a1),"r"(a2),"r"(a3),"r"(b0),"r"(b1))

#define LDSM4(R0,R1,R2,R3, A) \
    asm volatile("ldmatrix.sync.aligned.m8n8.x4.shared.b16 {%0,%1,%2,%3}, [%4];" \
                 : "=r"(R0),"=r"(R1),"=r"(R2),"=r"(R3) : "r"(A))
#define LDSM4T(R0,R1,R2,R3, A) \
    asm volatile("ldmatrix.sync.aligned.m8n8.x4.trans.shared.b16 {%0,%1,%2,%3}, [%4];" \
                 : "=r"(R0),"=r"(R1),"=r"(R2),"=r"(R3) : "r"(A))

// ---------------- merged f32 -> f16 weight conversion (+ conv k-major repack) ----------------
__global__ void f2h_all(const float* __restrict__ s0, const float* __restrict__ s1,
                        const float* __restrict__ s2, const float* __restrict__ s3,
                        const float* __restrict__ s4, const float* __restrict__ s5,
                        __half* __restrict__ dst)
{
    int i = blockIdx.x*256 + threadIdx.x;
    if (i < 49152)       dst[i] = __float2half_rn(s0[i]);
    else if (i < 65536)  dst[i] = __float2half_rn(s1[i - 49152]);
    else if (i < 98304)  dst[i] = __float2half_rn(s2[i - 65536]);
    else if (i < 131072) dst[i] = __float2half_rn(s3[i - 98304]);
    else if (i < 212992) {
        int j = i - 131072;                  // c1w: [128][640]
        int co = j / 640, rem = j % 640;
        int k = rem >> 7, ci = rem & 127;
        dst[i] = __float2half_rn(s4[co*640 + ci*5 + k]);
    } else if (i < 376832) {
        int j = i - 212992;                  // c2w: [256][640]
        int co = j / 640, rem = j % 640;
        int k = rem >> 7, c1 = rem & 127;
        dst[i] = __float2half_rn(s5[co*640 + c1*5 + k]);
    }
}

// ---------------- embed (writes f32 + f16) ----------------
__global__ void embed_kernel(const int* __restrict__ X, const float* __restrict__ sa,
                             const int* __restrict__ ptm,
                             const float* __restrict__ emb, const float* __restrict__ pemb,
                             float* __restrict__ x0, __half* __restrict__ x0h)
{
    int row = blockIdx.x;
    int t = threadIdx.x;
    float v;
    if (t < 120) v = emb[X[row]*120 + t] * sa[row];
    else         v = pemb[ptm[row]*8 + (t-120)];
    x0[(size_t)row*DM + t] = v;
    x0h[(size_t)row*DM + t] = __float2half_rn(v);
}

// ---------------- fp16 GEMM: 128x128 tile, 3-stage cp.async + ldmatrix ----------------
#define GSTH 40
__global__ __launch_bounds__(256,2) void gemm_f16(const __half* __restrict__ A,
                                                  const __half* __restrict__ W,
                                                  const float* __restrict__ bias,
                                                  float* __restrict__ Cf,
                                                  __half* __restrict__ Ch,
                                                  int M, int N, int K, int relu)
{
    __shared__ __align__(16) __half As[3][128*GSTH];
    __shared__ __align__(16) __half Bs[3][128*GSTH];
    int tid = threadIdx.x;
    int w = tid >> 5, lane = tid & 31, g = lane >> 2, tg = lane & 3;
    int wm = w & 3, wn = w >> 2;
    int row0 = blockIdx.y * 128, col0 = blockIdx.x * 128;

    int la = lane & 7, l8 = (lane >> 3) & 1, l16 = (lane >> 4) & 1;
    int rA = la + l8*8, cA = l16*8;
    int rB = la + l8*8, cB = l16*8;

    int lr = tid >> 2, lc8 = (tid & 3) * 8;
    int ar0 = row0 + lr;      if (ar0 > M-1) ar0 = M-1;
    int ar1 = row0 + lr + 64; if (ar1 > M-1) ar1 = M-1;
    const __half* ap0 = A + (size_t)ar0*K + lc8;
    const __half* ap1 = A + (size_t)ar1*K + lc8;
    const __half* wp0 = W + (size_t)(col0 + lr)*K + lc8;
    const __half* wp1 = W + (size_t)(col0 + lr + 64)*K + lc8;

    float c[2][8][4];
    #pragma unroll
    for (int mt=0; mt<2; ++mt)
        #pragma unroll
        for (int nt=0; nt<8; ++nt)
            #pragma unroll
            for (int i=0;i<4;++i) c[mt][nt][i]=0.f;

    int kt = K >> 5;

    #define GLOAD(s, k0) do { \
        CP16(sptr(&As[s][lr*GSTH + lc8]),      ap0 + (k0)); \
        CP16(sptr(&As[s][(lr+64)*GSTH + lc8]), ap1 + (k0)); \
        CP16(sptr(&Bs[s][lr*GSTH + lc8]),      wp0 + (k0)); \
        CP16(sptr(&Bs[s][(lr+64)*GSTH + lc8]), wp1 + (k0)); \
        CP_COMMIT(); \
    } while (0)

    GLOAD(0, 0);
    GLOAD(1, 32);

    for (int t = 0; t < kt; ++t) {
        int s = t % 3;
        CP_WAIT1();
        __syncthreads();
        if (t + 2 < kt) { GLOAD((t+2)%3, (t+2)*32); }
        else            { CP_COMMIT(); }

        #pragma unroll
        for (int ks = 0; ks < 2; ++ks) {
            int kk = ks*16;
            unsigned a[2][4], bq[4][4];
            #pragma unroll
            for (int mt = 0; mt < 2; ++mt)
                LDSM4(a[mt][0],a[mt][1],a[mt][2],a[mt][3],
                      sptr(&As[s][(wm*32 + mt*16 + rA)*GSTH + kk + cA]));
            #pragma unroll
            for (int p = 0; p < 4; ++p)
                LDSM4(bq[p][0],bq[p][1],bq[p][2],bq[p][3],
                      sptr(&Bs[s][(wn*64 + p*16 + rB)*GSTH + kk + cB]));
            #pragma unroll
            for (int p = 0; p < 4; ++p)
                #pragma unroll
                for (int q = 0; q < 2; ++q) {
                    int nt = p*2 + q;
                    MMA_F16(c[0][nt], a[0][0],a[0][1],a[0][2],a[0][3], bq[p][q], bq[p][q+2]);
                    MMA_F16(c[1][nt], a[1][0],a[1][1],a[1][2],a[1][3], bq[p][q], bq[p][q+2]);
                }
        }
    }
    #undef GLOAD

    #pragma unroll
    for (int mt = 0; mt < 2; ++mt) {
        int r0 = row0 + wm*32 + mt*16 + g;
        #pragma unroll
        for (int nt = 0; nt < 8; ++nt) {
            int cc = col0 + wn*64 + nt*8 + 2*tg;
            float b0v = bias[cc], b1v = bias[cc+1];
            float v0 = c[mt][nt][0] + b0v, v1 = c[mt][nt][1] + b1v;
            float v2 = c[mt][nt][2] + b0v, v3 = c[mt][nt][3] + b1v;
            if (relu) { v0=fmaxf(v0,0.f); v1=fmaxf(v1,0.f); v2=fmaxf(v2,0.f); v3=fmaxf(v3,0.f); }
            if (Cf) {
                if (r0 < M)     { float2 s2={v0,v1}; *(float2*)(Cf + (size_t)r0*N + cc) = s2; }
                if (r0 + 8 < M) { float2 s2={v2,v3}; *(float2*)(Cf + (size_t)(r0+8)*N + cc) = s2; }
            }
            if (Ch) {
                if (r0 < M)     *(__half2*)(Ch + (size_t)r0*N + cc)     = __floats2half2_rn(v0, v1);
                if (r0 + 8 < M) *(__half2*)(Ch + (size_t)(r0+8)*N + cc) = __floats2half2_rn(v2, v3);
            }
        }
    }
}

// ---------------- direct conv GEMM (im2col-free), f16 output ----------------
__global__ __launch_bounds__(256,2) void conv_gemm_f16(const __half* __restrict__ src,
                                                       const __half* __restrict__ W,
                                                       const float* __restrict__ bias,
                                                       __half* __restrict__ Ch,
                                                       int M, int N, int Lin, int Lout, int pad)
{
    __shared__ __align__(16) __half As[3][128*GSTH];
    __shared__ __align__(16) __half Bs[3][128*GSTH];
    int tid = threadIdx.x;
    int w = tid >> 5, lane = tid & 31, g = lane >> 2, tg = lane & 3;
    int wm = w & 3, wn = w >> 2;
    int row0 = blockIdx.y * 128, col0 = blockIdx.x * 128;

    int la = lane & 7, l8 = (lane >> 3) & 1, l16 = (lane >> 4) & 1;
    int rA = la + l8*8, cA = l16*8;
    int rB = la + l8*8, cB = l16*8;

    int lr = tid >> 2, lc8 = (tid & 3) * 8;
    int r0g = row0 + lr;      if (r0g > M-1) r0g = M-1;
    int r1g = row0 + lr + 64; if (r1g > M-1) r1g = M-1;
    int b0 = r0g / Lout, l0 = r0g % Lout;
    int b1 = r1g / Lout, l1 = r1g % Lout;
    const __half* wp0 = W + (size_t)(col0 + lr)*640 + lc8;
    const __half* wp1 = W + (size_t)(col0 + lr + 64)*640 + lc8;

    float c[2][8][4];
    #pragma unroll
    for (int mt=0; mt<2; ++mt)
        #pragma unroll
        for (int nt=0; nt<8; ++nt)
            #pragma unroll
            for (int i=0;i<4;++i) c[mt][nt][i]=0.f;

    #define CGLOAD(s, t) do { \
        int k_ = (t) >> 2, coff_ = ((t) & 3) * 32; \
        int ls0 = l0 + k_ - pad; \
        int ls1 = l1 + k_ - pad; \
        unsigned ok0 = ((unsigned)ls0 < (unsigned)Lin) ? 16u : 0u; \
        unsigned ok1 = ((unsigned)ls1 < (unsigned)Lin) ? 16u : 0u; \
        const __half* s0_ = src + ((size_t)(b0*Lin + (ok0 ? ls0 : 0)))*128 + coff_ + lc8; \
        const __half* s1_ = src + ((size_t)(b1*Lin + (ok1 ? ls1 : 0)))*128 + coff_ + lc8; \
        CP16Z(sptr(&As[s][lr*GSTH + lc8]),      s0_, ok0); \
        CP16Z(sptr(&As[s][(lr+64)*GSTH + lc8]), s1_, ok1); \
        CP16(sptr(&Bs[s][lr*GSTH + lc8]),      wp0 + (t)*32); \
        CP16(sptr(&Bs[s][(lr+64)*GSTH + lc8]), wp1 + (t)*32); \
        CP_COMMIT(); \
    } while (0)

    CGLOAD(0, 0);
    CGLOAD(1, 1);

    for (int t = 0; t < 20; ++t) {
        int s = t % 3;
        CP_WAIT1();
        __syncthreads();
        if (t + 2 < 20) { CGLOAD((t+2)%3, t+2); }
        else            { CP_COMMIT(); }

        #pragma unroll
        for (int ks = 0; ks < 2; ++ks) {
            int kk = ks*16;
            unsigned a[2][4], bq[4][4];
            #pragma unroll
            for (int mt = 0; mt < 2; ++mt)
                LDSM4(a[mt][0],a[mt][1],a[mt][2],a[mt][3],
                      sptr(&As[s][(wm*32 + mt*16 + rA)*GSTH + kk + cA]));
            #pragma unroll
            for (int p = 0; p < 4; ++p)
                LDSM4(bq[p][0],bq[p][1],bq[p][2],bq[p][3],
                      sptr(&Bs[s][(wn*64 + p*16 + rB)*GSTH + kk + cB]));
            #pragma unroll
            for (int p = 0; p < 4; ++p)
                #pragma unroll
                for (int q = 0; q < 2; ++q) {
                    int nt = p*2 + q;
                    MMA_F16(c[0][nt], a[0][0],a[0][1],a[0][2],a[0][3], bq[p][q], bq[p][q+2]);
                    MMA_F16(c[1][nt], a[1][0],a[1][1],a[1][2],a[1][3], bq[p][q], bq[p][q+2]);
                }
        }
    }
    #undef CGLOAD

    #pragma unroll
    for (int mt = 0; mt < 2; ++mt) {
        int r0 = row0 + wm*32 + mt*16 + g;
        #pragma unroll
        for (int nt = 0; nt < 8; ++nt) {
            int cc = col0 + wn*64 + nt*8 + 2*tg;
            float b0v = bias[cc], b1v = bias[cc+1];
            float v0 = c[mt][nt][0] + b0v, v1 = c[mt][nt][1] + b1v;
            float v2 = c[mt][nt][2] + b0v, v3 = c[mt][nt][3] + b1v;
            if (r0 < M)     *(__half2*)(Ch + (size_t)r0*N + cc)     = __floats2half2_rn(v0, v1);
            if (r0 + 8 < M) *(__half2*)(Ch + (size_t)(r0+8)*N + cc) = __floats2half2_rn(v2, v3);
        }
    }
}

// ---------------- fp16 flash attention (round-11 proven) ----------------
#define KSTH 40
#define RSN  2176
__global__ __launch_bounds__(256,2) void attn_f16(const __half* __restrict__ qkv,
                                                  const float* __restrict__ rpe,
                                                  __half* __restrict__ o)
{
    __shared__ __align__(16) __half Ks[2][64*KSTH];
    __shared__ __align__(16) __half Vs[2][64*KSTH];
    __shared__ __half2 rsh2[RSN];

    int tid = threadIdx.x;
    int w = tid >> 5, lane = tid & 31, g = lane >> 2, tg = lane & 3;
    int b = blockIdx.z, h = blockIdx.y;
    int q0 = blockIdx.x * 128;

    for (int i = tid; i < RSN; i += 256) {
        int d0 = i - 127 - q0;     d0 = d0 < -32 ? -32 : (d0 > 32 ? 32 : d0);
        int d1 = i + 1 - 127 - q0; d1 = d1 < -32 ? -32 : (d1 > 32 ? 32 : d1);
        rsh2[i] = __floats2half2_rn(rpe[(d0 + 32)*HH + h] * 1.44269504f,
                                    rpe[(d1 + 32)*HH + h] * 1.44269504f);
    }

    int la = lane & 7, l8 = (lane >> 3) & 1, l16 = (lane >> 4) & 1;
    int rB = la + l8*8, cB = l16*8;

    int r0 = q0 + w*16 + g, r1 = r0 + 8;
    int rbase = 127 - (w*16 + g) + 2*tg;

    const unsigned sc2  = h2u(__floats2half2_rn(SCALE2, SCALE2));
    const unsigned cl15 = h2u(__floats2half2_rn(15.f, 15.f));
    const unsigned ones = h2u(__floats2half2_rn(1.f, 1.f));

    unsigned aq[2][4];
    {
        const __half* qb = qkv + (size_t)(b*LSEQ)*384 + h*HDIM;
        #pragma unroll
        for (int kc = 0; kc < 2; ++kc) {
            int k = kc*16;
            aq[kc][0] = *(const unsigned*)(qb + (size_t)r0*384 + k + 2*tg);
            aq[kc][1] = *(const unsigned*)(qb + (size_t)r1*384 + k + 2*tg);
            aq[kc][2] = *(const unsigned*)(qb + (size_t)r0*384 + k + 2*tg + 8);
            aq[kc][3] = *(const unsigned*)(qb + (size_t)r1*384 + k + 2*tg + 8);
        }
    }

    float co[4][4];
    #pragma unroll
    for (int nt=0;nt<4;++nt)
        #pragma unroll
        for (int i=0;i<4;++i) co[nt][i]=0.f;
    float csum[4] = {0.f, 0.f, 0.f, 0.f};

    int srow = tid >> 2, scol = (tid & 3) * 8;
    const __half* kvbase = qkv + (size_t)(b*LSEQ)*384 + h*HDIM + 128;

    #define STAGE(s, j0) do { \
        const __half* kb_ = kvbase + (size_t)((j0) + srow)*384; \
        CP16(sptr(&Ks[s][srow*KSTH + scol]), kb_ + scol); \
        CP16(sptr(&Vs[s][srow*KSTH + scol]), kb_ + 128 + scol); \
        CP_COMMIT(); \
    } while (0)

    STAGE(0, 0);

    for (int jt = 0; jt < LSEQ/64; ++jt) {
        int s = jt & 1;
        if (jt + 1 < LSEQ/64) { STAGE(s^1, (jt+1)*64); CP_WAIT1(); }
        else                  { CP_WAIT0(); }
        __syncthreads();

        float cs[8][4];
        #pragma unroll
        for (int nt=0;nt<8;++nt)
            #pragma unroll
            for (int i=0;i<4;++i) cs[nt][i]=0.f;
        #pragma unroll
        for (int kc = 0; kc < 2; ++kc) {
            int kk = kc*16;
            unsigned bq[4][4];
            #pragma unroll
            for (int p = 0; p < 4; ++p)
                LDSM4(bq[p][0],bq[p][1],bq[p][2],bq[p][3],
                      sptr(&Ks[s][(p*16 + rB)*KSTH + kk + cB]));
            #pragma unroll
            for (int p = 0; p < 4; ++p)
                #pragma unroll
                for (int q = 0; q < 2; ++q)
                    MMA_F16(cs[p*2+q], aq[kc][0],aq[kc][1],aq[kc][2],aq[kc][3],
                            bq[p][q], bq[p][q+2]);
        }

        int ixb = jt*64 + rbase;
        unsigned ap[4][4];
        #pragma unroll
        for (int nt = 0; nt < 8; ++nt) {
            int ix = ixb + nt*8;
            unsigned x01 = h2u(__floats2half2_rn(cs[nt][0], cs[nt][1]));
            unsigned x23 = h2u(__floats2half2_rn(cs[nt][2], cs[nt][3]));
            unsigned b01 = *(const unsigned*)&rsh2[ix];
            unsigned b23 = *(const unsigned*)&rsh2[ix-8];
            asm("fma.rn.f16x2 %0, %1, %2, %3;" : "=r"(x01) : "r"(x01), "r"(sc2), "r"(b01));
            asm("fma.rn.f16x2 %0, %1, %2, %3;" : "=r"(x23) : "r"(x23), "r"(sc2), "r"(b23));
            asm("min.f16x2 %0, %1, %2;" : "=r"(x01) : "r"(x01), "r"(cl15));
            asm("min.f16x2 %0, %1, %2;" : "=r"(x23) : "r"(x23), "r"(cl15));
            asm("ex2.approx.f16x2 %0, %1;" : "=r"(x01) : "r"(x01));
            asm("ex2.approx.f16x2 %0, %1;" : "=r"(x23) : "r"(x23));
            int ks = nt >> 1, hi = nt & 1;
            ap[ks][hi*2+0] = x01;
            ap[ks][hi*2+1] = x23;
        }

        #pragma unroll
        for (int ks = 0; ks < 4; ++ks)
            MMA_F16(csum, ap[ks][0],ap[ks][1],ap[ks][2],ap[ks][3], ones, ones);

        #pragma unroll
        for (int ks = 0; ks < 4; ++ks) {
            int kk = ks*16;
            unsigned bv[2][4];
            #pragma unroll
            for (int dg = 0; dg < 2; ++dg)
                LDSM4T(bv[dg][0],bv[dg][1],bv[dg][2],bv[dg][3],
                       sptr(&Vs[s][(kk + la + l8*8)*KSTH + dg*16 + l16*8]));
            #pragma unroll
            for (int dg = 0; dg < 2; ++dg)
                #pragma unroll
                for (int q = 0; q < 2; ++q)
                    MMA_F16(co[dg*2+q], ap[ks][0],ap[ks][1],ap[ks][2],ap[ks][3],
                            bv[dg][q*2], bv[dg][q*2+1]);
        }
        __syncthreads();
    }
    #undef STAGE

    float inv0 = 1.f / csum[0], inv1 = 1.f / csum[2];

    #pragma unroll
    for (int nt2 = 0; nt2 < 4; ++nt2) {
        int d = nt2*8 + 2*tg;
        *(__half2*)(o + ((size_t)(b*LSEQ + r0))*DM + h*HDIM + d) =
            __floats2half2_rn(co[nt2][0]*inv0, co[nt2][1]*inv0);
        *(__half2*)(o + ((size_t)(b*LSEQ + r1))*DM + h*HDIM + d) =
            __floats2half2_rn(co[nt2][2]*inv1, co[nt2][3]*inv1);
    }
}

// ---------------- residual add + layernorm: warp per row, float4 ----------------
__global__ void add_ln_kernel(const float* __restrict__ a, const float* __restrict__ bres,
                              const float* __restrict__ g, const float* __restrict__ beta,
                              float* __restrict__ out, __half* __restrict__ outh)
{
    int row = blockIdx.x*8 + (threadIdx.x >> 5);
    int lane = threadIdx.x & 31;
    size_t off = (size_t)row*DM + lane*4;
    float4 va = *(const float4*)(a + off);
    float4 vb = *(const float4*)(bres + off);
    float4 v; v.x=va.x+vb.x; v.y=va.y+vb.y; v.z=va.z+vb.z; v.w=va.w+vb.w;
    float s  = v.x + v.y + v.z + v.w;
    float s2 = v.x*v.x + v.y*v.y + v.z*v.z + v.w*v.w;
    #pragma unroll
    for (int o2 = 16; o2; o2 >>= 1) {
        s  += __shfl_xor_sync(0xffffffffu, s,  o2);
        s2 += __shfl_xor_sync(0xffffffffu, s2, o2);
    }
    float mean = s * (1.f/128.f);
    float var  = s2 * (1.f/128.f) - mean*mean;
    float f = rsqrtf(var + EPSV);
    float4 gg = *(const float4*)(g + lane*4);
    float4 bb = *(const float4*)(beta + lane*4);
    float4 r;
    r.x = (v.x-mean)*f*gg.x + bb.x;
    r.y = (v.y-mean)*f*gg.y + bb.y;
    r.z = (v.z-mean)*f*gg.z + bb.z;
    r.w = (v.w-mean)*f*gg.w + bb.w;
    *(float4*)(out + off) = r;
    if (outh) {
        *(__half2*)(outh + off)     = __floats2half2_rn(r.x, r.y);
        *(__half2*)(outh + off + 2) = __floats2half2_rn(r.z, r.w);
    }
}

// ---------------- BN stats (f16 input) ----------------
__global__ void bnstats_kernel(const __half* __restrict__ y, int rows, int Cc, int rpb,
                               float* __restrict__ sum, float* __restrict__ sumsq)
{
    int c = threadIdx.x;
    int r0 = blockIdx.x * rpb;
    int r1 = r0 + rpb; if (r1 > rows) r1 = rows;
    float s = 0.f, s2 = 0.f;
    for (int r = r0; r < r1; ++r) {
        float v = __half2float(y[(size_t)r*Cc + c]);
        s += v; s2 += v*v;
    }
    atomicAdd(&sum[c], s);
    atomicAdd(&sumsq[c], s2);
}

// zero stats (n1) and z (n2) in one launch
__global__ void zero2_kernel(float* p1, int n1, float* p2, int n2)
{
    int i = blockIdx.x*256 + threadIdx.x;
    if (i < n1) p1[i] = 0.f;
    if (i < n2) p2[i] = 0.f;
}

// ---------------- BN + ReLU + maxpool(2): f16 in -> f16 out ----------------
__global__ void bnpool_kernel(const __half* __restrict__ y1,
                              const float* __restrict__ sum, const float* __restrict__ sq,
                              const float* __restrict__ g, const float* __restrict__ bb,
                              __half* __restrict__ p1)
{
    int c = threadIdx.x;
    int row2 = blockIdx.x;
    int b = row2 >> 10, l2 = row2 & 1023;
    float mean = sum[c]*(1.f/(float)BL);
    float var  = sq[c]*(1.f/(float)BL) - mean*mean;
    float f = rsqrtf(var + EPSV)*g[c];
    float v0 = (__half2float(y1[((size_t)(b*LSEQ + 2*l2  ))*C1 + c]) - mean)*f + bb[c];
    float v1 = (__half2float(y1[((size_t)(b*LSEQ + 2*l2+1))*C1 + c]) - mean)*f + bb[c];
    v0 = fmaxf(v0, 0.f); v1 = fmaxf(v1, 0.f);
    p1[(size_t)row2*C1 + c] = __float2half_rn(fmaxf(v0, v1));
}

// ---------------- BN + ReLU + global max (f16 in, atomicMax) ----------------
__global__ void gmax_kernel(const __half* __restrict__ y2,
                            const float* __restrict__ sum, const float* __restrict__ sq,
                            const float* __restrict__ g, const float* __restrict__ bb,
                            float* __restrict__ z)
{
    int c = threadIdx.x;
    int b = blockIdx.x;
    int part = blockIdx.y;
    float mean = sum[c]*(1.f/(float)M2);
    float var  = sq[c]*(1.f/(float)M2) - mean*mean;
    float f = rsqrtf(var + EPSV)*g[c];
    int l0 = part * 128;
    int l1 = l0 + 128; if (l1 > L2OUT) l1 = L2OUT;
    float vm = 0.f;
    for (int l = l0; l < l1; ++l) {
        float v = (__half2float(y2[((size_t)(b*L2OUT + l))*C2 + c]) - mean)*f + bb[c];
        vm = fmaxf(vm, v);
    }
    vm = fmaxf(vm, 0.f);
    atomicMax((int*)&z[b*C2 + c], __float_as_int(vm));
}

// ---------------- final fc ----------------
__global__ void fc_kernel(const float* __restrict__ z, const float* __restrict__ w,
                          const float* __restrict__ bias, float* __restrict__ out)
{
    int b = blockIdx.x, n = blockIdx.y;
    int t = threadIdx.x;
    float p = z[b*C2 + t] * w[n*C2 + t];
    #pragma unroll
    for (int off = 16; off; off >>= 1) p += __shfl_xor_sync(0xffffffffu, p, off);
    __shared__ float ws[8];
    if ((t & 31) == 0) ws[t >> 5] = p;
    __syncthreads();
    if (t == 0) {
        float s = 0.f;
        #pragma unroll
        for (int i = 0; i < 8; ++i) s += ws[i];
        out[b*2 + n] = s + bias[n];
    }
}

// ---------------- launch ----------------
extern "C" void kernel_launch(void* const* d_in, const int* in_sizes, int n_in,
                              void* d_out, int out_size)
{
    const int*   X    = (const int*)  d_in[0];
    const float* sa   = (const float*)d_in[1];
    const int*   ptm  = (const int*)  d_in[2];
    const float* emb  = (const float*)d_in[3];
    const float* pemb = (const float*)d_in[4];
    const float* rpe  = (const float*)d_in[5];
    const float* inw  = (const float*)d_in[6];
    const float* inb  = (const float*)d_in[7];
    const float* opw  = (const float*)d_in[8];
    const float* opb  = (const float*)d_in[9];
    const float* l1w  = (const float*)d_in[10];
    const float* l1b  = (const float*)d_in[11];
    const float* l2w  = (const float*)d_in[12];
    const float* l2b  = (const float*)d_in[13];
    const float* ln1g = (const float*)d_in[14];
    const float* ln1b = (const float*)d_in[15];
    const float* ln2g = (const float*)d_in[16];
    const float* ln2b = (const float*)d_in[17];
    const float* c1w  = (const float*)d_in[18];
    const float* c1b  = (const float*)d_in[19];
    const float* bn1g = (const float*)d_in[20];
    const float* bn1b = (const float*)d_in[21];
    const float* c2w  = (const float*)d_in[22];
    const float* c2b  = (const float*)d_in[23];
    const float* bn2g = (const float*)d_in[24];
    const float* bn2b = (const float*)d_in[25];
    const float* fcw  = (const float*)d_in[26];
    const float* fcb  = (const float*)d_in[27];
    float* out = (float*)d_out;

    float *x0,*tmp,*x1,*z,*stats;
    __half *x0h,*qkvh,*atth,*x1h,*ff1h,*x2h,*y1h,*p1h,*y2h,*wh;
    cudaGetSymbolAddress((void**)&x0,   g_x0);
    cudaGetSymbolAddress((void**)&x0h,  g_x0h);
    cudaGetSymbolAddress((void**)&qkvh, g_qkvh);
    cudaGetSymbolAddress((void**)&atth, g_atth);
    cudaGetSymbolAddress((void**)&tmp,  g_tmp);
    cudaGetSymbolAddress((void**)&x1,   g_x1);
    cudaGetSymbolAddress((void**)&x1h,  g_x1h);
    cudaGetSymbolAddress((void**)&ff1h, g_ff1h);
    cudaGetSymbolAddress((void**)&x2h,  g_x2h);
    cudaGetSymbolAddress((void**)&y1h,  g_y1h);
    cudaGetSymbolAddress((void**)&p1h,  g_p1h);
    cudaGetSymbolAddress((void**)&y2h,  g_y2h);
    cudaGetSymbolAddress((void**)&z,    g_z);
    cudaGetSymbolAddress((void**)&stats,g_stats);
    cudaGetSymbolAddress((void**)&wh,   g_wh);

    __half* inwh = wh;
    __half* opwh = wh + 49152;
    __half* l1wh = wh + 65536;
    __half* l2wh = wh + 98304;
    __half* c1wh = wh + 131072;
    __half* c2wh = wh + 212992;

    // 0) merged weight conversion (f32 -> f16, conv weights repacked k-major)
    f2h_all<<<(376832 + 255)/256, 256>>>(inw, opw, l1w, l2w, c1w, c2w, wh);

    // 1) embedding + concat (f32 + f16)
    embed_kernel<<<BL, 128>>>(X, sa, ptm, emb, pemb, x0, x0h);

    // 2) qkv projection -> f16 [BL,384]
    gemm_f16<<<dim3(384/128, BL/128), 256>>>(x0h, inwh, inb, nullptr, qkvh, BL, 3*DM, DM, 0);

    // 3) attention -> f16
    attn_f16<<<dim3(LSEQ/128, HH, BB), 256>>>(qkvh, rpe, atth);

    // 4) out projection -> f32 tmp
    gemm_f16<<<dim3(DM/128, BL/128), 256>>>(atth, opwh, opb, tmp, nullptr, BL, DM, DM, 0);

    // 5) x1 = LN(x0 + attn_out) (f32 + f16)
    add_ln_kernel<<<BL/8, 256>>>(x0, tmp, ln1g, ln1b, x1, x1h);

    // 6) FF
    gemm_f16<<<dim3(FFD/128, BL/128), 256>>>(x1h, l1wh, l1b, nullptr, ff1h, BL, FFD, DM, 1);
    gemm_f16<<<dim3(DM/128,  BL/128), 256>>>(ff1h, l2wh, l2b, tmp, nullptr, BL, DM, FFD, 0);

    // 7) x2 = LN(x1 + ff) -> f16 (for direct conv1)
    add_ln_kernel<<<BL/8, 256>>>(x1, tmp, ln2g, ln2b, x1, x2h);

    // 8) conv1 direct GEMM -> y1h (f16)
    conv_gemm_f16<<<dim3(C1/128, BL/128), 256>>>(x2h, c1wh, c1b, y1h, BL, C1, LSEQ, LSEQ, 2);

    // 9) zero stats + z, BN1 stats
    zero2_kernel<<<16, 256>>>(stats, 2*C1 + 2*C2, z, BB*C2);
    bnstats_kernel<<<128, C1>>>(y1h, BL, C1, 256, stats, stats + C1);

    // 10) BN1 + ReLU + maxpool2 -> f16 p1
    bnpool_kernel<<<BB*L2HALF, C1>>>(y1h, stats, stats + C1, bn1g, bn1b, p1h);

    // 11) conv2 direct GEMM -> y2h (f16)
    conv_gemm_f16<<<dim3(C2/128, (M2+127)/128), 256>>>(p1h, c2wh, c2b, y2h, M2, C2, L2HALF, L2OUT, 0);

    // 12) BN2 stats
    bnstats_kernel<<<128, C2>>>(y2h, M2, C2, 128, stats + 2*C1, stats + 2*C1 + C2);

    // 13) BN2 + ReLU + global max
    gmax_kernel<<<dim3(BB, 8), C2>>>(y2h, stats + 2*C1, stats + 2*C1 + C2, bn2g, bn2b, z);

    // 14) fc
    fc_kernel<<<dim3(BB, 2), 256>>>(z, fcw, fcb, out);
}